// round 7
// baseline (speedup 1.0000x reference)
#include <cuda_runtime.h>
#include <cuda_bf16.h>

#define S_LEN 512
#define HID   500
#define G3    1500
#define VOC   50000
#define NVT   391          // ceil(50000/128)
#define RGRID 32

// ---------------- static device scratch ----------------
__device__ float gGiEnc[S_LEN * G3];
__device__ float gGiDec[S_LEN * G3];
__device__ float gHping[512];
__device__ float gHpong[512];
__device__ float gHfinal[512];
__device__ float gDecHs[S_LEN * HID];
__device__ float gPmax[S_LEN * NVT];
__device__ float gPsum[S_LEN * NVT];
__device__ int   gPidx[S_LEN * NVT];
__device__ float gTlogit[S_LEN];
__device__ float gNll[S_LEN];
__device__ unsigned gBarCount;
__device__ volatile unsigned gBarSense;

// ---------------- helpers ----------------
__device__ __forceinline__ unsigned long long f22ull(float x, float y) {
    unsigned long long u;
    asm("mov.b64 %0, {%1, %2};" : "=l"(u) : "f"(x), "f"(y));
    return u;
}
__device__ __forceinline__ void ull2f2(unsigned long long u, float& x, float& y) {
    asm("mov.b64 {%0, %1}, %2;" : "=f"(x), "=f"(y) : "l"(u));
}
__device__ __forceinline__ void ffma2(unsigned long long& d, unsigned long long a, unsigned long long b) {
    asm("fma.rn.f32x2 %0, %1, %2, %0;" : "+l"(d) : "l"(a), "l"(b));
}

// =====================================================================
// K1: gi = gather(emb, tok)[relu if dec] @ Wih^T + bih   for enc & dec
// grid (12, 4, 2): x = g-tile(128 of 1500), y = t-tile(128 of 512), z = mode
// =====================================================================
__global__ __launch_bounds__(256, 1) void gi_gemm_kernel(
    const int* __restrict__ encTok, const int* __restrict__ tgtTok,
    const float* __restrict__ encEmb, const float* __restrict__ decEmb,
    const float* __restrict__ encWih, const float* __restrict__ decWih,
    const float* __restrict__ encBih, const float* __restrict__ decBih)
{
    const int mode = blockIdx.z;
    const float* emb  = mode ? decEmb : encEmb;
    const float* W    = mode ? decWih : encWih;
    const float* bias = mode ? decBih : encBih;
    float* out = mode ? gGiDec : gGiEnc;

    const int t0 = blockIdx.y * 128;
    const int g0 = blockIdx.x * 128;

    __shared__ __align__(16) unsigned long long As[10][128];
    __shared__ __align__(16) unsigned long long Bs[10][128];
    __shared__ int   sTok[128];
    __shared__ float sBias[128];

    const int tid = threadIdx.x;
    if (tid < 128) {
        int t = t0 + tid;
        int tok;
        if (mode) tok = (t == 0) ? 0 : tgtTok[t - 1];   // teacher forcing, PAD first
        else      tok = encTok[t];
        sTok[tid] = tok;
        int g = g0 + tid;
        sBias[tid] = (g < G3) ? bias[g] : 0.f;
    }
    __syncthreads();

    unsigned long long acc[8][8];
#pragma unroll
    for (int i = 0; i < 8; i++)
#pragma unroll
        for (int j = 0; j < 8; j++) acc[i][j] = 0ull;

    const int ty = tid >> 4, tx = tid & 15;

    for (int kc = 0; kc < 25; kc++) {
        const int kb = kc * 20;
#pragma unroll
        for (int r = 0; r < 5; r++) {
            int id  = tid + r * 256;
            int k2  = id >> 7;
            int col = id & 127;
            const float* ap = emb + (size_t)sTok[col] * HID + kb + k2 * 2;
            float2 av = *(const float2*)ap;
            if (mode) { av.x = fmaxf(av.x, 0.f); av.y = fmaxf(av.y, 0.f); }
            As[k2][col] = f22ull(av.x, av.y);
            int g = g0 + col;
            float2 bv = make_float2(0.f, 0.f);
            if (g < G3) bv = *(const float2*)(W + (size_t)g * HID + kb + k2 * 2);
            Bs[k2][col] = f22ull(bv.x, bv.y);
        }
        __syncthreads();
#pragma unroll
        for (int k2 = 0; k2 < 10; k2++) {
            unsigned long long a[8], b[8];
            const ulonglong2* ap = (const ulonglong2*)&As[k2][ty << 3];
            ulonglong2 q;
            q = ap[0]; a[0] = q.x; a[1] = q.y;
            q = ap[1]; a[2] = q.x; a[3] = q.y;
            q = ap[2]; a[4] = q.x; a[5] = q.y;
            q = ap[3]; a[6] = q.x; a[7] = q.y;
            const ulonglong2* bp = (const ulonglong2*)&Bs[k2][tx << 3];
            q = bp[0]; b[0] = q.x; b[1] = q.y;
            q = bp[1]; b[2] = q.x; b[3] = q.y;
            q = bp[2]; b[4] = q.x; b[5] = q.y;
            q = bp[3]; b[6] = q.x; b[7] = q.y;
#pragma unroll
            for (int i = 0; i < 8; i++)
#pragma unroll
                for (int j = 0; j < 8; j++) ffma2(acc[i][j], a[i], b[j]);
        }
        __syncthreads();
    }

#pragma unroll
    for (int i = 0; i < 8; i++) {
        int t = t0 + (ty << 3) + i;
#pragma unroll
        for (int j = 0; j < 8; j++) {
            int g = g0 + (tx << 3) + j;
            if (g < G3) {
                float x, y; ull2f2(acc[i][j], x, y);
                out[(size_t)t * G3 + g] = x + y + sBias[(tx << 3) + j];
            }
        }
    }
}

// ---------------- grid barrier (snapshot sense-reversing; replay-safe) ----------------
__device__ __forceinline__ void grid_bar() {
    __threadfence();
    __syncthreads();
    if (threadIdx.x == 0) {
        unsigned snap = gBarSense;
        unsigned old = atomicAdd(&gBarCount, 1u);
        if (old == RGRID - 1u) {
            gBarCount = 0u;
            __threadfence();
            gBarSense = snap + 1u;
        } else {
            while (gBarSense == snap) { }
        }
    }
    __syncthreads();
}

// =====================================================================
// K2: GRU recurrence, persistent. 32 blocks x 512 threads.
// Warp w of block b owns hidden unit j = b*16 + w; Whh rows in registers.
// =====================================================================
__global__ __launch_bounds__(512, 1) void gru_rec_kernel(
    const float* __restrict__ Whh, const float* __restrict__ bhh,
    const float* __restrict__ h0_in, float* __restrict__ dOut, int mode)
{
    const float* gi = mode ? gGiDec : gGiEnc;
    const int warp = threadIdx.x >> 5;
    const int lane = threadIdx.x & 31;
    const int j = blockIdx.x * 16 + warp;
    const bool jv = (j < HID);

    float wr[16], wz[16], wn[16];
#pragma unroll
    for (int i = 0; i < 16; i++) {
        int k = lane + (i << 5);
        bool kv = jv && (k < HID);
        wr[i] = kv ? Whh[(size_t)j * HID + k]             : 0.f;
        wz[i] = kv ? Whh[(size_t)(j + HID) * HID + k]     : 0.f;
        wn[i] = kv ? Whh[(size_t)(j + 2 * HID) * HID + k] : 0.f;
    }
    float br = 0.f, bz = 0.f, bn = 0.f;
    if (jv) { br = bhh[j]; bz = bhh[j + HID]; bn = bhh[j + 2 * HID]; }

    if (blockIdx.x == 0) {
        int t = threadIdx.x;
        const float* h0 = mode ? gHfinal : h0_in;
        __stcg(&gHping[t], (t < HID) ? h0[t] : 0.f);
        __stcg(&gHpong[t], 0.f);
    }
    grid_bar();

    for (int s = 0; s < S_LEN; s++) {
        const float* cur = (s & 1) ? gHpong : gHping;
        float* nxt = (s & 1) ? gHping : gHpong;

        float h[16];
#pragma unroll
        for (int i = 0; i < 16; i++) h[i] = __ldcg(cur + lane + (i << 5));

        float gir = 0.f, giz = 0.f, gin = 0.f, hold = 0.f;
        if (lane == 0 && jv) {
            const float* gis = gi + (size_t)s * G3 + j;
            gir = gis[0]; giz = gis[HID]; gin = gis[2 * HID];
            hold = __ldcg(cur + j);
        }

        float ar = 0.f, az = 0.f, an = 0.f;
#pragma unroll
        for (int i = 0; i < 16; i++) {
            ar = fmaf(wr[i], h[i], ar);
            az = fmaf(wz[i], h[i], az);
            an = fmaf(wn[i], h[i], an);
        }
#pragma unroll
        for (int off = 16; off; off >>= 1) {
            ar += __shfl_xor_sync(0xffffffffu, ar, off);
            az += __shfl_xor_sync(0xffffffffu, az, off);
            an += __shfl_xor_sync(0xffffffffu, an, off);
        }

        if (lane == 0 && jv) {
            float r = 1.f / (1.f + expf(-(gir + ar + br)));
            float z = 1.f / (1.f + expf(-(giz + az + bz)));
            float n = tanhf(gin + r * (an + bn));
            float hnew = (1.f - z) * n + z * hold;
            __stcg(nxt + j, hnew);
            if (mode) gDecHs[(size_t)s * HID + j] = hnew;
        }
        grid_bar();
    }

    if (!mode && blockIdx.x == 0 && threadIdx.x < HID) {
        float hv = __ldcg(((S_LEN & 1) ? gHpong : gHping) + threadIdx.x);
        gHfinal[threadIdx.x] = hv;
        dOut[1 + threadIdx.x] = hv;          // enc_h output slice
    }
}

// =====================================================================
// K3: logits = dec_hs @ outW^T + outB, fused per-tile softmax partials.
// grid (NVT, 4): x = v-tile(128), y = t-tile(128). Logits never hit HBM.
// =====================================================================
__global__ __launch_bounds__(256, 1) void logits_kernel(
    const float* __restrict__ outW, const float* __restrict__ outB,
    const int* __restrict__ target)
{
    const int t0 = blockIdx.y * 128;
    const int v0 = blockIdx.x * 128;

    __shared__ __align__(16) unsigned long long As[10][128];  // 10 KB
    __shared__ __align__(16) unsigned long long Bs[10][128];  // 10 KB
    __shared__ float sOb[128];
    __shared__ float sRowMax[128];
    __shared__ int   sRowIdx[128];

    const int tid = threadIdx.x;
    if (tid < 128) {
        int v = v0 + tid;
        sOb[tid] = (v < VOC) ? outB[v] : 0.f;
    }

    unsigned long long acc[8][8];
#pragma unroll
    for (int i = 0; i < 8; i++)
#pragma unroll
        for (int j = 0; j < 8; j++) acc[i][j] = 0ull;

    const int ty = tid >> 4, tx = tid & 15;

    for (int kc = 0; kc < 25; kc++) {
        const int kb = kc * 20;
#pragma unroll
        for (int r = 0; r < 5; r++) {
            int id  = tid + r * 256;
            int k2  = id >> 7;
            int col = id & 127;
            float2 av = *(const float2*)(gDecHs + (size_t)(t0 + col) * HID + kb + k2 * 2);
            As[k2][col] = f22ull(av.x, av.y);
            int v = v0 + col;
            float2 bv = make_float2(0.f, 0.f);
            if (v < VOC) bv = *(const float2*)(outW + (size_t)v * HID + kb + k2 * 2);
            Bs[k2][col] = f22ull(bv.x, bv.y);
        }
        __syncthreads();
#pragma unroll
        for (int k2 = 0; k2 < 10; k2++) {
            unsigned long long a[8], b[8];
            const ulonglong2* ap = (const ulonglong2*)&As[k2][ty << 3];
            ulonglong2 q;
            q = ap[0]; a[0] = q.x; a[1] = q.y;
            q = ap[1]; a[2] = q.x; a[3] = q.y;
            q = ap[2]; a[4] = q.x; a[5] = q.y;
            q = ap[3]; a[6] = q.x; a[7] = q.y;
            const ulonglong2* bp = (const ulonglong2*)&Bs[k2][tx << 3];
            q = bp[0]; b[0] = q.x; b[1] = q.y;
            q = bp[1]; b[2] = q.x; b[3] = q.y;
            q = bp[2]; b[4] = q.x; b[5] = q.y;
            q = bp[3]; b[6] = q.x; b[7] = q.y;
#pragma unroll
            for (int i = 0; i < 8; i++)
#pragma unroll
                for (int j = 0; j < 8; j++) ffma2(acc[i][j], a[i], b[j]);
        }
        __syncthreads();
    }

    // ---- fused epilogue: per-(row, vtile) max / argmax / sum-exp ----
    float* sM = (float*)As;                 // [128][16] reuse, 8KB
    int*   sI = (int*)Bs;                   // [128][16] reuse, 8KB

    // pass 1: per-thread max/argmax + target-logit capture
#pragma unroll
    for (int i = 0; i < 8; i++) {
        int row = (ty << 3) + i;
        int t = t0 + row;
        int tgt = target[t];
        float lmax = -1e30f; int lidx = 0;
#pragma unroll
        for (int j = 0; j < 8; j++) {
            int v = v0 + (tx << 3) + j;
            if (v < VOC) {
                float x, y; ull2f2(acc[i][j], x, y);
                float logit = x + y + sOb[(tx << 3) + j];
                if (logit > lmax) { lmax = logit; lidx = v; }
                if (v == tgt) gTlogit[t] = logit;
            }
        }
        sM[row * 16 + tx] = lmax;
        sI[row * 16 + tx] = lidx;
    }
    __syncthreads();

    if (tid < 128) {
        float m = -1e30f; int idx = 0x7fffffff;
        for (int e = 0; e < 16; e++) {
            float me = sM[tid * 16 + e]; int ie = sI[tid * 16 + e];
            if (me > m || (me == m && ie < idx)) { m = me; idx = ie; }
        }
        sRowMax[tid] = m; sRowIdx[tid] = idx;
    }
    __syncthreads();

    // pass 2: sum exp(logit - tileRowMax)
    float* sS = (float*)As;                 // reuse again
#pragma unroll
    for (int i = 0; i < 8; i++) {
        int row = (ty << 3) + i;
        float rmax = sRowMax[row];
        float lsum = 0.f;
#pragma unroll
        for (int j = 0; j < 8; j++) {
            int v = v0 + (tx << 3) + j;
            if (v < VOC) {
                float x, y; ull2f2(acc[i][j], x, y);
                lsum += expf(x + y + sOb[(tx << 3) + j] - rmax);
            }
        }
        sS[row * 16 + tx] = lsum;
    }
    __syncthreads();

    if (tid < 128) {
        float s = 0.f;
        for (int e = 0; e < 16; e++) s += sS[tid * 16 + e];
        int t = t0 + tid;
        size_t o = (size_t)t * NVT + blockIdx.x;
        gPmax[o] = sRowMax[tid];
        gPidx[o] = sRowIdx[tid];
        gPsum[o] = s;
    }
}

// =====================================================================
// K4: per-row cross-tile reduction -> argmax + NLL.   grid(512,128)
// =====================================================================
__global__ __launch_bounds__(128) void finalize_kernel(float* __restrict__ dOut)
{
    const int t = blockIdx.x;
    const int tid = threadIdx.x;
    __shared__ float rm[128];
    __shared__ int   ri[128];
    __shared__ float rs[128];

    float m = -1e30f; int idx = 0x7fffffff;
    for (int vt = tid; vt < NVT; vt += 128) {
        float mv = gPmax[(size_t)t * NVT + vt];
        int   iv = gPidx[(size_t)t * NVT + vt];
        if (mv > m || (mv == m && iv < idx)) { m = mv; idx = iv; }
    }
    rm[tid] = m; ri[tid] = idx;
    __syncthreads();
    for (int off = 64; off; off >>= 1) {
        if (tid < off) {
            float m2 = rm[tid + off]; int i2 = ri[tid + off];
            if (m2 > rm[tid] || (m2 == rm[tid] && i2 < ri[tid])) { rm[tid] = m2; ri[tid] = i2; }
        }
        __syncthreads();
    }
    float gmax = rm[0]; int gidx = ri[0];

    float s = 0.f;
    for (int vt = tid; vt < NVT; vt += 128) {
        size_t o = (size_t)t * NVT + vt;
        s += gPsum[o] * expf(gPmax[o] - gmax);
    }
    rs[tid] = s;
    __syncthreads();
    for (int off = 64; off; off >>= 1) {
        if (tid < off) rs[tid] += rs[tid + off];
        __syncthreads();
    }
    if (tid == 0) {
        float lse = gmax + logf(rs[0]);
        gNll[t] = lse - gTlogit[t];
        dOut[1 + HID + t] = (float)gidx;     // decoder_outputs
    }
}

// =====================================================================
// K5: loss = sum(gNll).   1 block x 512
// =====================================================================
__global__ __launch_bounds__(512) void loss_kernel(float* __restrict__ dOut)
{
    __shared__ float rs[512];
    int tid = threadIdx.x;
    rs[tid] = gNll[tid];
    __syncthreads();
    for (int off = 256; off; off >>= 1) {
        if (tid < off) rs[tid] += rs[tid + off];
        __syncthreads();
    }
    if (tid == 0) dOut[0] = rs[0];
}

// =====================================================================
extern "C" void kernel_launch(void* const* d_in, const int* in_sizes, int n_in,
                              void* d_out, int out_size)
{
    const int*   encTok = (const int*)d_in[0];
    const int*   tgtTok = (const int*)d_in[1];
    const float* encH0  = (const float*)d_in[2];
    const float* encEmb = (const float*)d_in[3];
    const float* encWih = (const float*)d_in[4];
    const float* encWhh = (const float*)d_in[5];
    const float* encBih = (const float*)d_in[6];
    const float* encBhh = (const float*)d_in[7];
    const float* decEmb = (const float*)d_in[8];
    const float* decWih = (const float*)d_in[9];
    const float* decWhh = (const float*)d_in[10];
    const float* decBih = (const float*)d_in[11];
    const float* decBhh = (const float*)d_in[12];
    const float* outW   = (const float*)d_in[13];
    const float* outB   = (const float*)d_in[14];
    float* out = (float*)d_out;

    gi_gemm_kernel<<<dim3(12, 4, 2), 256>>>(encTok, tgtTok, encEmb, decEmb,
                                            encWih, decWih, encBih, decBih);
    gru_rec_kernel<<<RGRID, 512>>>(encWhh, encBhh, encH0, out, 0);
    gru_rec_kernel<<<RGRID, 512>>>(decWhh, decBhh, encH0, out, 1);
    logits_kernel<<<dim3(NVT, 4), 256>>>(outW, outB, tgtTok);
    finalize_kernel<<<512, 128>>>(out);
    loss_kernel<<<1, 512>>>(out);
}

// round 8
// speedup vs baseline: 1.0943x; 1.0943x over previous
#include <cuda_runtime.h>
#include <cuda_bf16.h>

#define S_LEN 512
#define HID   500
#define G3    1500
#define VOC   50000
#define NVT   391          // ceil(50000/128)
#define RBLK  25           // recurrence blocks
#define RWPB  20           // warps per recurrence block (25*20 = 500 = HID)

// ---------------- static device scratch ----------------
__device__ float gGiEnc[S_LEN * G3];
__device__ float gGiDec[S_LEN * G3];
__device__ float gHping[512];
__device__ float gHpong[512];
__device__ float gHfinal[512];
__device__ float gDecHs[S_LEN * HID];
__device__ float gPmax[S_LEN * NVT];
__device__ float gPsum[S_LEN * NVT];
__device__ int   gPidx[S_LEN * NVT];
__device__ float gTlogit[S_LEN];
__device__ float gNll[S_LEN];
__device__ unsigned gBarCount;
__device__ unsigned gBarSense;

// ---------------- helpers ----------------
__device__ __forceinline__ unsigned long long f22ull(float x, float y) {
    unsigned long long u;
    asm("mov.b64 %0, {%1, %2};" : "=l"(u) : "f"(x), "f"(y));
    return u;
}
__device__ __forceinline__ void ull2f2(unsigned long long u, float& x, float& y) {
    asm("mov.b64 {%0, %1}, %2;" : "=f"(x), "=f"(y) : "l"(u));
}
__device__ __forceinline__ void ffma2(unsigned long long& d, unsigned long long a, unsigned long long b) {
    asm("fma.rn.f32x2 %0, %1, %2, %0;" : "+l"(d) : "l"(a), "l"(b));
}
__device__ __forceinline__ unsigned ld_acq(const unsigned* p) {
    unsigned v;
    asm volatile("ld.acquire.gpu.global.u32 %0, [%1];" : "=r"(v) : "l"(p) : "memory");
    return v;
}
__device__ __forceinline__ void st_rel(unsigned* p, unsigned v) {
    asm volatile("st.release.gpu.global.u32 [%0], %1;" :: "l"(p), "r"(v) : "memory");
}
__device__ __forceinline__ void st_rlx(unsigned* p, unsigned v) {
    asm volatile("st.relaxed.gpu.global.u32 [%0], %1;" :: "l"(p), "r"(v) : "memory");
}
__device__ __forceinline__ unsigned atom_add_rel(unsigned* p, unsigned v) {
    unsigned old;
    asm volatile("atom.release.gpu.global.add.u32 %0, [%1], %2;" : "=r"(old) : "l"(p), "r"(v) : "memory");
    return old;
}

// =====================================================================
// K1: gi = gather(emb, tok)[relu if dec] @ Wih^T + bih   for enc & dec
// grid (12, 4, 2). Conflict-free B fragments: thread tx owns cols tx+16m.
// =====================================================================
__global__ __launch_bounds__(256, 1) void gi_gemm_kernel(
    const int* __restrict__ encTok, const int* __restrict__ tgtTok,
    const float* __restrict__ encEmb, const float* __restrict__ decEmb,
    const float* __restrict__ encWih, const float* __restrict__ decWih,
    const float* __restrict__ encBih, const float* __restrict__ decBih)
{
    const int mode = blockIdx.z;
    const float* emb  = mode ? decEmb : encEmb;
    const float* W    = mode ? decWih : encWih;
    const float* bias = mode ? decBih : encBih;
    float* out = mode ? gGiDec : gGiEnc;

    const int t0 = blockIdx.y * 128;
    const int g0 = blockIdx.x * 128;

    __shared__ __align__(16) unsigned long long As[10][128];
    __shared__ __align__(16) unsigned long long Bs[10][128];
    __shared__ int   sTok[128];
    __shared__ float sBias[128];

    const int tid = threadIdx.x;
    if (tid < 128) {
        int t = t0 + tid;
        int tok;
        if (mode) tok = (t == 0) ? 0 : tgtTok[t - 1];   // teacher forcing, PAD first
        else      tok = encTok[t];
        sTok[tid] = tok;
        int g = g0 + tid;
        sBias[tid] = (g < G3) ? bias[g] : 0.f;
    }
    __syncthreads();

    unsigned long long acc[8][8];
#pragma unroll
    for (int i = 0; i < 8; i++)
#pragma unroll
        for (int j = 0; j < 8; j++) acc[i][j] = 0ull;

    const int ty = tid >> 4, tx = tid & 15;

    for (int kc = 0; kc < 25; kc++) {
        const int kb = kc * 20;
#pragma unroll
        for (int r = 0; r < 5; r++) {
            int id  = tid + r * 256;
            int k2  = id >> 7;
            int col = id & 127;
            const float* ap = emb + (size_t)sTok[col] * HID + kb + k2 * 2;
            float2 av = *(const float2*)ap;
            if (mode) { av.x = fmaxf(av.x, 0.f); av.y = fmaxf(av.y, 0.f); }
            As[k2][col] = f22ull(av.x, av.y);
            int g = g0 + col;
            float2 bv = make_float2(0.f, 0.f);
            if (g < G3) bv = *(const float2*)(W + (size_t)g * HID + kb + k2 * 2);
            Bs[k2][col] = f22ull(bv.x, bv.y);
        }
        __syncthreads();
#pragma unroll
        for (int k2 = 0; k2 < 10; k2++) {
            unsigned long long a[8], b[8];
            const ulonglong2* ap = (const ulonglong2*)&As[k2][ty << 3];
            ulonglong2 q;
            q = ap[0]; a[0] = q.x; a[1] = q.y;
            q = ap[1]; a[2] = q.x; a[3] = q.y;
            q = ap[2]; a[4] = q.x; a[5] = q.y;
            q = ap[3]; a[6] = q.x; a[7] = q.y;
#pragma unroll
            for (int m = 0; m < 8; m++) b[m] = Bs[k2][tx + (m << 4)];
#pragma unroll
            for (int i = 0; i < 8; i++)
#pragma unroll
                for (int j = 0; j < 8; j++) ffma2(acc[i][j], a[i], b[j]);
        }
        __syncthreads();
    }

#pragma unroll
    for (int i = 0; i < 8; i++) {
        int t = t0 + (ty << 3) + i;
#pragma unroll
        for (int m = 0; m < 8; m++) {
            int g = g0 + tx + (m << 4);
            if (g < G3) {
                float x, y; ull2f2(acc[i][m], x, y);
                out[(size_t)t * G3 + g] = x + y + sBias[tx + (m << 4)];
            }
        }
    }
}

// =====================================================================
// K2: GRU recurrence, persistent. 25 blocks x 640 threads (500 warps).
// Warp w of block b owns hidden unit j = b*20 + w; Whh rows in registers.
// Barrier: monotonic sense, release-atomic arrive + acquire-poll.
// =====================================================================
__global__ __launch_bounds__(640, 1) void gru_rec_kernel(
    const float* __restrict__ Whh, const float* __restrict__ bhh,
    const float* __restrict__ h0_in, float* __restrict__ dOut, int mode)
{
    const float* gi = mode ? gGiDec : gGiEnc;
    const int warp = threadIdx.x >> 5;
    const int lane = threadIdx.x & 31;
    const int j = blockIdx.x * RWPB + warp;   // 0..499, always valid

    // snapshot sense BEFORE first arrival (race-free: flip happens only
    // after all blocks have arrived, hence after all snapshots)
    const unsigned V0 = ld_acq(&gBarSense);

    float wr[16], wz[16], wn[16];
#pragma unroll
    for (int i = 0; i < 16; i++) {
        int k = lane + (i << 5);
        bool kv = (k < HID);
        wr[i] = kv ? Whh[(size_t)j * HID + k]             : 0.f;
        wz[i] = kv ? Whh[(size_t)(j + HID) * HID + k]     : 0.f;
        wn[i] = kv ? Whh[(size_t)(j + 2 * HID) * HID + k] : 0.f;
    }
    const float br = bhh[j], bz = bhh[j + HID], bn = bhh[j + 2 * HID];

    if (blockIdx.x == 0 && threadIdx.x < 512) {
        int t = threadIdx.x;
        const float* h0 = mode ? gHfinal : h0_in;
        __stcg(&gHping[t], (t < HID) ? h0[t] : 0.f);
        __stcg(&gHpong[t], 0.f);
    }

    // prefetch gi for step 0 (gGi written by previous kernel launch)
    float gir = 0.f, giz = 0.f, gin = 0.f;
    if (lane == 0) {
        const float* gis = gi + j;
        gir = gis[0]; giz = gis[HID]; gin = gis[2 * HID];
    }

    // ---- barrier 1: init visible ----
    __syncthreads();
    if (threadIdx.x == 0) {
        unsigned old = atom_add_rel(&gBarCount, 1u);
        if (old == RBLK - 1u) { st_rlx(&gBarCount, 0u); st_rel(&gBarSense, V0 + 1u); }
    }
    while (ld_acq(&gBarSense) < V0 + 1u) { }

    for (int s = 0; s < S_LEN; s++) {
        const float* cur = (s & 1) ? gHpong : gHping;
        float* nxt = (s & 1) ? gHping : gHpong;

        float h[16];
#pragma unroll
        for (int i = 0; i < 16; i++) h[i] = __ldcg(cur + lane + (i << 5));
        float hold = 0.f;
        if (lane == 0) hold = __ldcg(cur + j);

        float ar = 0.f, az = 0.f, an = 0.f;
#pragma unroll
        for (int i = 0; i < 16; i++) {
            ar = fmaf(wr[i], h[i], ar);
            az = fmaf(wz[i], h[i], az);
            an = fmaf(wn[i], h[i], an);
        }
#pragma unroll
        for (int off = 16; off; off >>= 1) {
            ar += __shfl_xor_sync(0xffffffffu, ar, off);
            az += __shfl_xor_sync(0xffffffffu, az, off);
            an += __shfl_xor_sync(0xffffffffu, an, off);
        }

        if (lane == 0) {
            float r = 1.f / (1.f + expf(-(gir + ar + br)));
            float z = 1.f / (1.f + expf(-(giz + az + bz)));
            float n = tanhf(gin + r * (an + bn));
            float hnew = (1.f - z) * n + z * hold;
            __stcg(nxt + j, hnew);
            if (mode) gDecHs[(size_t)s * HID + j] = hnew;
            // prefetch next step's gi — latency hides in the barrier wait
            if (s + 1 < S_LEN) {
                const float* gis = gi + (size_t)(s + 1) * G3 + j;
                gir = gis[0]; giz = gis[HID]; gin = gis[2 * HID];
            }
        }

        const unsigned tgt = V0 + 2u + (unsigned)s;
        __syncthreads();
        if (threadIdx.x == 0) {
            unsigned old = atom_add_rel(&gBarCount, 1u);
            if (old == RBLK - 1u) { st_rlx(&gBarCount, 0u); st_rel(&gBarSense, tgt); }
        }
        while (ld_acq(&gBarSense) < tgt) { }
    }

    if (!mode && blockIdx.x == 0 && threadIdx.x < HID) {
        float hv = __ldcg(((S_LEN & 1) ? gHpong : gHping) + threadIdx.x);
        gHfinal[threadIdx.x] = hv;
        dOut[1 + threadIdx.x] = hv;          // enc_h output slice
    }
}

// =====================================================================
// K3: logits = dec_hs @ outW^T + outB, fused per-tile softmax partials.
// grid (NVT, 4). Conflict-free B fragments: thread tx owns cols tx+16m.
// Logits never hit HBM.
// =====================================================================
__global__ __launch_bounds__(256, 1) void logits_kernel(
    const float* __restrict__ outW, const float* __restrict__ outB,
    const int* __restrict__ target)
{
    const int t0 = blockIdx.y * 128;
    const int v0 = blockIdx.x * 128;

    __shared__ __align__(16) unsigned long long As[10][128];  // 10 KB
    __shared__ __align__(16) unsigned long long Bs[10][128];  // 10 KB
    __shared__ float sOb[128];
    __shared__ float sRowMax[128];
    __shared__ int   sRowIdx[128];

    const int tid = threadIdx.x;
    if (tid < 128) {
        int v = v0 + tid;
        sOb[tid] = (v < VOC) ? outB[v] : 0.f;
    }

    unsigned long long acc[8][8];
#pragma unroll
    for (int i = 0; i < 8; i++)
#pragma unroll
        for (int j = 0; j < 8; j++) acc[i][j] = 0ull;

    const int ty = tid >> 4, tx = tid & 15;

    for (int kc = 0; kc < 25; kc++) {
        const int kb = kc * 20;
#pragma unroll
        for (int r = 0; r < 5; r++) {
            int id  = tid + r * 256;
            int k2  = id >> 7;
            int col = id & 127;
            float2 av = *(const float2*)(gDecHs + (size_t)(t0 + col) * HID + kb + k2 * 2);
            As[k2][col] = f22ull(av.x, av.y);
            int v = v0 + col;
            float2 bv = make_float2(0.f, 0.f);
            if (v < VOC) bv = *(const float2*)(outW + (size_t)v * HID + kb + k2 * 2);
            Bs[k2][col] = f22ull(bv.x, bv.y);
        }
        __syncthreads();
#pragma unroll
        for (int k2 = 0; k2 < 10; k2++) {
            unsigned long long a[8], b[8];
            const ulonglong2* ap = (const ulonglong2*)&As[k2][ty << 3];
            ulonglong2 q;
            q = ap[0]; a[0] = q.x; a[1] = q.y;
            q = ap[1]; a[2] = q.x; a[3] = q.y;
            q = ap[2]; a[4] = q.x; a[5] = q.y;
            q = ap[3]; a[6] = q.x; a[7] = q.y;
#pragma unroll
            for (int m = 0; m < 8; m++) b[m] = Bs[k2][tx + (m << 4)];
#pragma unroll
            for (int i = 0; i < 8; i++)
#pragma unroll
                for (int j = 0; j < 8; j++) ffma2(acc[i][j], a[i], b[j]);
        }
        __syncthreads();
    }

    // ---- fused epilogue: per-(row, vtile) max / argmax / sum-exp ----
    float* sM = (float*)As;                 // [128][16] reuse
    int*   sI = (int*)Bs;                   // [128][16] reuse

#pragma unroll
    for (int i = 0; i < 8; i++) {
        int row = (ty << 3) + i;
        int t = t0 + row;
        int tgt = target[t];
        float lmax = -1e30f; int lidx = 0;
#pragma unroll
        for (int m = 0; m < 8; m++) {
            int v = v0 + tx + (m << 4);
            if (v < VOC) {
                float x, y; ull2f2(acc[i][m], x, y);
                float logit = x + y + sOb[tx + (m << 4)];
                if (logit > lmax) { lmax = logit; lidx = v; }
                if (v == tgt) gTlogit[t] = logit;
            }
        }
        sM[row * 16 + tx] = lmax;
        sI[row * 16 + tx] = lidx;
    }
    __syncthreads();

    if (tid < 128) {
        float m = -1e30f; int idx = 0x7fffffff;
        for (int e = 0; e < 16; e++) {
            float me = sM[tid * 16 + e]; int ie = sI[tid * 16 + e];
            if (me > m || (me == m && ie < idx)) { m = me; idx = ie; }
        }
        sRowMax[tid] = m; sRowIdx[tid] = idx;
    }
    __syncthreads();

    float* sS = (float*)As;                 // reuse again
#pragma unroll
    for (int i = 0; i < 8; i++) {
        int row = (ty << 3) + i;
        float rmax = sRowMax[row];
        float lsum = 0.f;
#pragma unroll
        for (int m = 0; m < 8; m++) {
            int v = v0 + tx + (m << 4);
            if (v < VOC) {
                float x, y; ull2f2(acc[i][m], x, y);
                lsum += expf(x + y + sOb[tx + (m << 4)] - rmax);
            }
        }
        sS[row * 16 + tx] = lsum;
    }
    __syncthreads();

    if (tid < 128) {
        float s = 0.f;
        for (int e = 0; e < 16; e++) s += sS[tid * 16 + e];
        int t = t0 + tid;
        size_t o = (size_t)t * NVT + blockIdx.x;
        gPmax[o] = sRowMax[tid];
        gPidx[o] = sRowIdx[tid];
        gPsum[o] = s;
    }
}

// =====================================================================
// K4: per-row cross-tile reduction -> argmax + NLL.   grid(512) x 128
// =====================================================================
__global__ __launch_bounds__(128) void finalize_kernel(float* __restrict__ dOut)
{
    const int t = blockIdx.x;
    const int tid = threadIdx.x;
    __shared__ float rm[128];
    __shared__ int   ri[128];
    __shared__ float rs[128];

    float m = -1e30f; int idx = 0x7fffffff;
    for (int vt = tid; vt < NVT; vt += 128) {
        float mv = gPmax[(size_t)t * NVT + vt];
        int   iv = gPidx[(size_t)t * NVT + vt];
        if (mv > m || (mv == m && iv < idx)) { m = mv; idx = iv; }
    }
    rm[tid] = m; ri[tid] = idx;
    __syncthreads();
    for (int off = 64; off; off >>= 1) {
        if (tid < off) {
            float m2 = rm[tid + off]; int i2 = ri[tid + off];
            if (m2 > rm[tid] || (m2 == rm[tid] && i2 < ri[tid])) { rm[tid] = m2; ri[tid] = i2; }
        }
        __syncthreads();
    }
    float gmax = rm[0]; int gidx = ri[0];

    float s = 0.f;
    for (int vt = tid; vt < NVT; vt += 128) {
        size_t o = (size_t)t * NVT + vt;
        s += gPsum[o] * expf(gPmax[o] - gmax);
    }
    rs[tid] = s;
    __syncthreads();
    for (int off = 64; off; off >>= 1) {
        if (tid < off) rs[tid] += rs[tid + off];
        __syncthreads();
    }
    if (tid == 0) {
        float lse = gmax + logf(rs[0]);
        gNll[t] = lse - gTlogit[t];
        dOut[1 + HID + t] = (float)gidx;     // decoder_outputs
    }
}

// =====================================================================
// K5: loss = sum(gNll).   1 block x 512
// =====================================================================
__global__ __launch_bounds__(512) void loss_kernel(float* __restrict__ dOut)
{
    __shared__ float rs[512];
    int tid = threadIdx.x;
    rs[tid] = gNll[tid];
    __syncthreads();
    for (int off = 256; off; off >>= 1) {
        if (tid < off) rs[tid] += rs[tid + off];
        __syncthreads();
    }
    if (tid == 0) dOut[0] = rs[0];
}

// =====================================================================
extern "C" void kernel_launch(void* const* d_in, const int* in_sizes, int n_in,
                              void* d_out, int out_size)
{
    const int*   encTok = (const int*)d_in[0];
    const int*   tgtTok = (const int*)d_in[1];
    const float* encH0  = (const float*)d_in[2];
    const float* encEmb = (const float*)d_in[3];
    const float* encWih = (const float*)d_in[4];
    const float* encWhh = (const float*)d_in[5];
    const float* encBih = (const float*)d_in[6];
    const float* encBhh = (const float*)d_in[7];
    const float* decEmb = (const float*)d_in[8];
    const float* decWih = (const float*)d_in[9];
    const float* decWhh = (const float*)d_in[10];
    const float* decBih = (const float*)d_in[11];
    const float* decBhh = (const float*)d_in[12];
    const float* outW   = (const float*)d_in[13];
    const float* outB   = (const float*)d_in[14];
    float* out = (float*)d_out;

    gi_gemm_kernel<<<dim3(12, 4, 2), 256>>>(encTok, tgtTok, encEmb, decEmb,
                                            encWih, decWih, encBih, decBih);
    gru_rec_kernel<<<RBLK, 640>>>(encWhh, encBhh, encH0, out, 0);
    gru_rec_kernel<<<RBLK, 640>>>(decWhh, decBhh, encH0, out, 1);
    logits_kernel<<<dim3(NVT, 4), 256>>>(outW, outB, tgtTok);
    finalize_kernel<<<512, 128>>>(out);
    loss_kernel<<<1, 512>>>(out);
}

// round 9
// speedup vs baseline: 1.2456x; 1.1383x over previous
#include <cuda_runtime.h>
#include <cuda_bf16.h>

#define S_LEN 512
#define HID   500
#define G3    1500
#define VOC   50000
#define NVT   391          // ceil(50000/128)
#define RBLK  25           // recurrence blocks
#define RWPB  20           // warps per recurrence block (25*20 = 500 = HID)

// ---------------- static device scratch ----------------
__device__ float gGiEnc[S_LEN * G3];
__device__ float gGiDec[S_LEN * G3];
__device__ __align__(16) float gHbuf[2][512];
__device__ __align__(16) float gHfinal[512];
__device__ float gDecHs[S_LEN * HID];
__device__ float gPmax[S_LEN * NVT];
__device__ float gPsum[S_LEN * NVT];
__device__ int   gPidx[S_LEN * NVT];
__device__ float gTlogit[S_LEN];
__device__ float gNll[S_LEN];
__device__ __align__(128) unsigned gBarCount;   // line-isolated
__device__ __align__(128) unsigned gBarSense;   // line-isolated

// ---------------- helpers ----------------
__device__ __forceinline__ unsigned long long f22ull(float x, float y) {
    unsigned long long u;
    asm("mov.b64 %0, {%1, %2};" : "=l"(u) : "f"(x), "f"(y));
    return u;
}
__device__ __forceinline__ void ull2f2(unsigned long long u, float& x, float& y) {
    asm("mov.b64 {%0, %1}, %2;" : "=f"(x), "=f"(y) : "l"(u));
}
__device__ __forceinline__ void ffma2(unsigned long long& d, unsigned long long a, unsigned long long b) {
    asm("fma.rn.f32x2 %0, %1, %2, %0;" : "+l"(d) : "l"(a), "l"(b));
}
__device__ __forceinline__ unsigned ld_acq(const unsigned* p) {
    unsigned v;
    asm volatile("ld.acquire.gpu.global.u32 %0, [%1];" : "=r"(v) : "l"(p) : "memory");
    return v;
}
__device__ __forceinline__ void st_rel(unsigned* p, unsigned v) {
    asm volatile("st.release.gpu.global.u32 [%0], %1;" :: "l"(p), "r"(v) : "memory");
}
__device__ __forceinline__ void st_rlx(unsigned* p, unsigned v) {
    asm volatile("st.relaxed.gpu.global.u32 [%0], %1;" :: "l"(p), "r"(v) : "memory");
}
__device__ __forceinline__ unsigned atom_add_rel(unsigned* p, unsigned v) {
    unsigned old;
    asm volatile("atom.release.gpu.global.add.u32 %0, [%1], %2;" : "=r"(old) : "l"(p), "r"(v) : "memory");
    return old;
}

// =====================================================================
// K1: gi = gather(emb, tok)[relu if dec] @ Wih^T + bih   for enc & dec
// grid (12, 4, 2). Conflict-free B fragments: thread tx owns cols tx+16m.
// =====================================================================
__global__ __launch_bounds__(256, 1) void gi_gemm_kernel(
    const int* __restrict__ encTok, const int* __restrict__ tgtTok,
    const float* __restrict__ encEmb, const float* __restrict__ decEmb,
    const float* __restrict__ encWih, const float* __restrict__ decWih,
    const float* __restrict__ encBih, const float* __restrict__ decBih)
{
    const int mode = blockIdx.z;
    const float* emb  = mode ? decEmb : encEmb;
    const float* W    = mode ? decWih : encWih;
    const float* bias = mode ? decBih : encBih;
    float* out = mode ? gGiDec : gGiEnc;

    const int t0 = blockIdx.y * 128;
    const int g0 = blockIdx.x * 128;

    __shared__ __align__(16) unsigned long long As[10][128];
    __shared__ __align__(16) unsigned long long Bs[10][128];
    __shared__ int   sTok[128];
    __shared__ float sBias[128];

    const int tid = threadIdx.x;
    if (tid < 128) {
        int t = t0 + tid;
        int tok;
        if (mode) tok = (t == 0) ? 0 : tgtTok[t - 1];   // teacher forcing, PAD first
        else      tok = encTok[t];
        sTok[tid] = tok;
        int g = g0 + tid;
        sBias[tid] = (g < G3) ? bias[g] : 0.f;
    }
    __syncthreads();

    unsigned long long acc[8][8];
#pragma unroll
    for (int i = 0; i < 8; i++)
#pragma unroll
        for (int j = 0; j < 8; j++) acc[i][j] = 0ull;

    const int ty = tid >> 4, tx = tid & 15;

    for (int kc = 0; kc < 25; kc++) {
        const int kb = kc * 20;
#pragma unroll
        for (int r = 0; r < 5; r++) {
            int id  = tid + r * 256;
            int k2  = id >> 7;
            int col = id & 127;
            const float* ap = emb + (size_t)sTok[col] * HID + kb + k2 * 2;
            float2 av = *(const float2*)ap;
            if (mode) { av.x = fmaxf(av.x, 0.f); av.y = fmaxf(av.y, 0.f); }
            As[k2][col] = f22ull(av.x, av.y);
            int g = g0 + col;
            float2 bv = make_float2(0.f, 0.f);
            if (g < G3) bv = *(const float2*)(W + (size_t)g * HID + kb + k2 * 2);
            Bs[k2][col] = f22ull(bv.x, bv.y);
        }
        __syncthreads();
#pragma unroll
        for (int k2 = 0; k2 < 10; k2++) {
            unsigned long long a[8], b[8];
            const ulonglong2* ap = (const ulonglong2*)&As[k2][ty << 3];
            ulonglong2 q;
            q = ap[0]; a[0] = q.x; a[1] = q.y;
            q = ap[1]; a[2] = q.x; a[3] = q.y;
            q = ap[2]; a[4] = q.x; a[5] = q.y;
            q = ap[3]; a[6] = q.x; a[7] = q.y;
#pragma unroll
            for (int m = 0; m < 8; m++) b[m] = Bs[k2][tx + (m << 4)];
#pragma unroll
            for (int i = 0; i < 8; i++)
#pragma unroll
                for (int j = 0; j < 8; j++) ffma2(acc[i][j], a[i], b[j]);
        }
        __syncthreads();
    }

#pragma unroll
    for (int i = 0; i < 8; i++) {
        int t = t0 + (ty << 3) + i;
#pragma unroll
        for (int m = 0; m < 8; m++) {
            int g = g0 + tx + (m << 4);
            if (g < G3) {
                float x, y; ull2f2(acc[i][m], x, y);
                out[(size_t)t * G3 + g] = x + y + sBias[tx + (m << 4)];
            }
        }
    }
}

// =====================================================================
// K2: GRU recurrence, persistent. 25 blocks x 640 threads (500 warps).
// h lives in per-CTA shared memory; exchanged once per step through L2
// with ONE coalesced store + ONE cooperative float4 reload per CTA.
// Barrier: tid0-only acquire-poll, release-atomic arrive, padded words.
// =====================================================================
__global__ __launch_bounds__(640, 1) void gru_rec_kernel(
    const float* __restrict__ Whh, const float* __restrict__ bhh,
    const float* __restrict__ h0_in, float* __restrict__ dOut, int mode)
{
    const float* gi = mode ? gGiDec : gGiEnc;
    const int tid  = threadIdx.x;
    const int warp = tid >> 5;
    const int lane = tid & 31;
    const int j = blockIdx.x * RWPB + warp;   // 0..499

    __shared__ __align__(16) float sH[512];
    __shared__ float sStage[RWPB];

    // snapshot sense BEFORE first arrival (race-free: flips only after all arrive)
    const unsigned V0 = ld_acq(&gBarSense);

    // weights: lane holds k = i*128 + lane*4 + c  (float4-friendly, zero-padded)
    float wr[16], wz[16], wn[16];
#pragma unroll
    for (int i = 0; i < 4; i++) {
        int kb = (i << 7) + (lane << 2);
        if (kb + 3 < HID) {
            float4 a = *(const float4*)(Whh + (size_t)j * HID + kb);
            float4 b = *(const float4*)(Whh + (size_t)(j + HID) * HID + kb);
            float4 c = *(const float4*)(Whh + (size_t)(j + 2 * HID) * HID + kb);
            wr[i*4+0]=a.x; wr[i*4+1]=a.y; wr[i*4+2]=a.z; wr[i*4+3]=a.w;
            wz[i*4+0]=b.x; wz[i*4+1]=b.y; wz[i*4+2]=b.z; wz[i*4+3]=b.w;
            wn[i*4+0]=c.x; wn[i*4+1]=c.y; wn[i*4+2]=c.z; wn[i*4+3]=c.w;
        } else {
#pragma unroll
            for (int c = 0; c < 4; c++) {
                wr[i*4+c] = 0.f; wz[i*4+c] = 0.f; wn[i*4+c] = 0.f;
            }
        }
    }
    const float br = bhh[j], bz = bhh[j + HID], bn = bhh[j + 2 * HID];

    // init sH from h0 (enc) / gHfinal (dec); pad 500..511 with zeros
    if (tid < 128) {
        float4 v = make_float4(0.f, 0.f, 0.f, 0.f);
        if (tid < 125) {
            if (mode) v = *(const float4*)(gHfinal + tid * 4);
            else      v = *(const float4*)(h0_in + tid * 4);   // exactly 500 floats
        }
        *(float4*)(sH + tid * 4) = v;
    }

    // prefetch gi for step 0
    float gir = 0.f, giz = 0.f, gin = 0.f;
    if (lane == 0) {
        const float* g0 = gi + j;
        gir = g0[0]; giz = g0[HID]; gin = g0[2 * HID];
    }
    __syncthreads();

    for (int s = 0; s < S_LEN; s++) {
        // h from shared (conflict-free float4: lanes stride 16B)
        float h[16];
#pragma unroll
        for (int i = 0; i < 4; i++) {
            float4 v = *(const float4*)(sH + (i << 7) + (lane << 2));
            h[i*4+0]=v.x; h[i*4+1]=v.y; h[i*4+2]=v.z; h[i*4+3]=v.w;
        }
        float ar = 0.f, az = 0.f, an = 0.f;
#pragma unroll
        for (int i = 0; i < 16; i++) {
            ar = fmaf(wr[i], h[i], ar);
            az = fmaf(wz[i], h[i], az);
            an = fmaf(wn[i], h[i], an);
        }
#pragma unroll
        for (int off = 16; off; off >>= 1) {
            ar += __shfl_xor_sync(0xffffffffu, ar, off);
            az += __shfl_xor_sync(0xffffffffu, az, off);
            an += __shfl_xor_sync(0xffffffffu, an, off);
        }
        if (lane == 0) {
            float hold = sH[j];
            float r = 1.f / (1.f + expf(-(gir + ar + br)));
            float z = 1.f / (1.f + expf(-(giz + az + bz)));
            float n = tanhf(gin + r * (an + bn));
            sStage[warp] = (1.f - z) * n + z * hold;
            if (s + 1 < S_LEN) {           // prefetch next gi — hides under barrier
                const float* gs = gi + (size_t)(s + 1) * G3 + j;
                gir = gs[0]; giz = gs[HID]; gin = gs[2 * HID];
            }
        }
        __syncthreads();                   // A: stage complete

        float* hb = gHbuf[s & 1];
        const unsigned tgt = V0 + 1u + (unsigned)s;
        if (warp == 0) {
            if (lane < RWPB) {             // ONE coalesced 20-float store
                float v = sStage[lane];
                int col = blockIdx.x * RWPB + lane;
                __stcg(hb + col, v);
                if (mode) __stcg(gDecHs + (size_t)s * HID + col, v);
            }
            __syncwarp();
            if (lane == 0) {
                unsigned old = atom_add_rel(&gBarCount, 1u);
                if (old == RBLK - 1u) { st_rlx(&gBarCount, 0u); st_rel(&gBarSense, tgt); }
                while (ld_acq(&gBarSense) != tgt) { }    // tid0-only poll
            }
        }
        __syncthreads();                   // B: release observed block-wide

        if (tid < 125) {                   // cooperative full-h reload (4 requests)
            float4 v = __ldcg((const float4*)hb + tid);
            *(float4*)(sH + tid * 4) = v;
        }
        __syncthreads();                   // C: sH ready
    }

    if (!mode && blockIdx.x == 0) {
        if (tid < 512) gHfinal[tid] = sH[tid];
        if (tid < HID) dOut[1 + tid] = sH[tid];   // enc_h output slice
    }
}

// =====================================================================
// K3: logits = dec_hs @ outW^T + outB, double-buffered smem, fused
// per-tile softmax partials. grid (NVT, 4). Logits never hit HBM.
// =====================================================================
__global__ __launch_bounds__(256, 1) void logits_kernel(
    const float* __restrict__ outW, const float* __restrict__ outB,
    const int* __restrict__ target)
{
    const int t0 = blockIdx.y * 128;
    const int v0 = blockIdx.x * 128;

    __shared__ __align__(16) unsigned long long As[2][10][128];  // 20 KB
    __shared__ __align__(16) unsigned long long Bs[2][10][128];  // 20 KB
    __shared__ float sOb[128];
    __shared__ float sRowMax[128];
    __shared__ int   sRowIdx[128];

    const int tid = threadIdx.x;
    if (tid < 128) {
        int v = v0 + tid;
        sOb[tid] = (v < VOC) ? outB[v] : 0.f;
    }

    unsigned long long acc[8][8];
#pragma unroll
    for (int i = 0; i < 8; i++)
#pragma unroll
        for (int j = 0; j < 8; j++) acc[i][j] = 0ull;

    const int ty = tid >> 4, tx = tid & 15;
    const int myV = v0 + (tid & 127);
    const bool vOk = (myV < VOC);
    const float* aBase = gDecHs + (size_t)(t0 + (tid & 127)) * HID;
    const float* bBase = outW + (size_t)(vOk ? myV : 0) * HID;

    // prologue: chunk 0 straight to smem buffer 0
    {
#pragma unroll
        for (int r = 0; r < 5; r++) {
            int id  = tid + r * 256;
            int k2  = id >> 7;
            int col = id & 127;
            float2 av = *(const float2*)(gDecHs + (size_t)(t0 + col) * HID + k2 * 2);
            As[0][k2][col] = f22ull(av.x, av.y);
            int v = v0 + col;
            float2 bv = make_float2(0.f, 0.f);
            if (v < VOC) bv = *(const float2*)(outW + (size_t)v * HID + k2 * 2);
            Bs[0][k2][col] = f22ull(bv.x, bv.y);
        }
    }
    __syncthreads();

    for (int kc = 0; kc < 25; kc++) {
        const int cur = kc & 1, nxt = cur ^ 1;

        // issue next chunk's loads first (latency hides under compute)
        unsigned long long pa[5], pb[5];
        if (kc < 24) {
            const int kb = (kc + 1) * 20;
#pragma unroll
            for (int r = 0; r < 5; r++) {
                int id  = tid + r * 256;
                int k2  = id >> 7;
                int col = id & 127;
                float2 av = *(const float2*)(gDecHs + (size_t)(t0 + col) * HID + kb + k2 * 2);
                pa[r] = f22ull(av.x, av.y);
                int v = v0 + col;
                float2 bv = make_float2(0.f, 0.f);
                if (v < VOC) bv = *(const float2*)(outW + (size_t)v * HID + kb + k2 * 2);
                pb[r] = f22ull(bv.x, bv.y);
            }
        }

#pragma unroll
        for (int k2 = 0; k2 < 10; k2++) {
            unsigned long long a[8], b[8];
            const ulonglong2* ap = (const ulonglong2*)&As[cur][k2][ty << 3];
            ulonglong2 q;
            q = ap[0]; a[0] = q.x; a[1] = q.y;
            q = ap[1]; a[2] = q.x; a[3] = q.y;
            q = ap[2]; a[4] = q.x; a[5] = q.y;
            q = ap[3]; a[6] = q.x; a[7] = q.y;
#pragma unroll
            for (int m = 0; m < 8; m++) b[m] = Bs[cur][k2][tx + (m << 4)];
#pragma unroll
            for (int i = 0; i < 8; i++)
#pragma unroll
                for (int j = 0; j < 8; j++) ffma2(acc[i][j], a[i], b[j]);
        }

        if (kc < 24) {
#pragma unroll
            for (int r = 0; r < 5; r++) {
                int id  = tid + r * 256;
                int k2  = id >> 7;
                int col = id & 127;
                As[nxt][k2][col] = pa[r];
                Bs[nxt][k2][col] = pb[r];
            }
        }
        __syncthreads();
    }

    // ---- fused epilogue: per-(row, vtile) max / argmax / sum-exp ----
    float* sM = (float*)As;                 // reuse
    int*   sI = (int*)Bs;                   // reuse

#pragma unroll
    for (int i = 0; i < 8; i++) {
        int row = (ty << 3) + i;
        int t = t0 + row;
        int tgt = target[t];
        float lmax = -1e30f; int lidx = 0;
#pragma unroll
        for (int m = 0; m < 8; m++) {
            int v = v0 + tx + (m << 4);
            if (v < VOC) {
                float x, y; ull2f2(acc[i][m], x, y);
                float logit = x + y + sOb[tx + (m << 4)];
                if (logit > lmax) { lmax = logit; lidx = v; }
                if (v == tgt) gTlogit[t] = logit;
            }
        }
        sM[row * 16 + tx] = lmax;
        sI[row * 16 + tx] = lidx;
    }
    __syncthreads();

    if (tid < 128) {
        float m = -1e30f; int idx = 0x7fffffff;
        for (int e = 0; e < 16; e++) {
            float me = sM[tid * 16 + e]; int ie = sI[tid * 16 + e];
            if (me > m || (me == m && ie < idx)) { m = me; idx = ie; }
        }
        sRowMax[tid] = m; sRowIdx[tid] = idx;
    }
    __syncthreads();

    float* sS = (float*)As;                 // reuse again
#pragma unroll
    for (int i = 0; i < 8; i++) {
        int row = (ty << 3) + i;
        float rmax = sRowMax[row];
        float lsum = 0.f;
#pragma unroll
        for (int m = 0; m < 8; m++) {
            int v = v0 + tx + (m << 4);
            if (v < VOC) {
                float x, y; ull2f2(acc[i][m], x, y);
                lsum += expf(x + y + sOb[tx + (m << 4)] - rmax);
            }
        }
        sS[row * 16 + tx] = lsum;
    }
    __syncthreads();

    if (tid < 128) {
        float s = 0.f;
        for (int e = 0; e < 16; e++) s += sS[tid * 16 + e];
        int t = t0 + tid;
        size_t o = (size_t)t * NVT + blockIdx.x;
        gPmax[o] = sRowMax[tid];
        gPidx[o] = sRowIdx[tid];
        gPsum[o] = s;
    }
}

// =====================================================================
// K4: per-row cross-tile reduction -> argmax + NLL.   grid(512) x 128
// =====================================================================
__global__ __launch_bounds__(128) void finalize_kernel(float* __restrict__ dOut)
{
    const int t = blockIdx.x;
    const int tid = threadIdx.x;
    __shared__ float rm[128];
    __shared__ int   ri[128];
    __shared__ float rs[128];

    float m = -1e30f; int idx = 0x7fffffff;
    for (int vt = tid; vt < NVT; vt += 128) {
        float mv = gPmax[(size_t)t * NVT + vt];
        int   iv = gPidx[(size_t)t * NVT + vt];
        if (mv > m || (mv == m && iv < idx)) { m = mv; idx = iv; }
    }
    rm[tid] = m; ri[tid] = idx;
    __syncthreads();
    for (int off = 64; off; off >>= 1) {
        if (tid < off) {
            float m2 = rm[tid + off]; int i2 = ri[tid + off];
            if (m2 > rm[tid] || (m2 == rm[tid] && i2 < ri[tid])) { rm[tid] = m2; ri[tid] = i2; }
        }
        __syncthreads();
    }
    float gmax = rm[0]; int gidx = ri[0];

    float s = 0.f;
    for (int vt = tid; vt < NVT; vt += 128) {
        size_t o = (size_t)t * NVT + vt;
        s += gPsum[o] * expf(gPmax[o] - gmax);
    }
    rs[tid] = s;
    __syncthreads();
    for (int off = 64; off; off >>= 1) {
        if (tid < off) rs[tid] += rs[tid + off];
        __syncthreads();
    }
    if (tid == 0) {
        float lse = gmax + logf(rs[0]);
        gNll[t] = lse - gTlogit[t];
        dOut[1 + HID + t] = (float)gidx;     // decoder_outputs
    }
}

// =====================================================================
// K5: loss = sum(gNll).   1 block x 512
// =====================================================================
__global__ __launch_bounds__(512) void loss_kernel(float* __restrict__ dOut)
{
    __shared__ float rs[512];
    int tid = threadIdx.x;
    rs[tid] = gNll[tid];
    __syncthreads();
    for (int off = 256; off; off >>= 1) {
        if (tid < off) rs[tid] += rs[tid + off];
        __syncthreads();
    }
    if (tid == 0) dOut[0] = rs[0];
}

// =====================================================================
extern "C" void kernel_launch(void* const* d_in, const int* in_sizes, int n_in,
                              void* d_out, int out_size)
{
    const int*   encTok = (const int*)d_in[0];
    const int*   tgtTok = (const int*)d_in[1];
    const float* encH0  = (const float*)d_in[2];
    const float* encEmb = (const float*)d_in[3];
    const float* encWih = (const float*)d_in[4];
    const float* encWhh = (const float*)d_in[5];
    const float* encBih = (const float*)d_in[6];
    const float* encBhh = (const float*)d_in[7];
    const float* decEmb = (const float*)d_in[8];
    const float* decWih = (const float*)d_in[9];
    const float* decWhh = (const float*)d_in[10];
    const float* decBih = (const float*)d_in[11];
    const float* decBhh = (const float*)d_in[12];
    const float* outW   = (const float*)d_in[13];
    const float* outB   = (const float*)d_in[14];
    float* out = (float*)d_out;

    gi_gemm_kernel<<<dim3(12, 4, 2), 256>>>(encTok, tgtTok, encEmb, decEmb,
                                            encWih, decWih, encBih, decBih);
    gru_rec_kernel<<<RBLK, 640>>>(encWhh, encBhh, encH0, out, 0);
    gru_rec_kernel<<<RBLK, 640>>>(decWhh, decBhh, encH0, out, 1);
    logits_kernel<<<dim3(NVT, 4), 256>>>(outW, outB, tgtTok);
    finalize_kernel<<<512, 128>>>(out);
    loss_kernel<<<1, 512>>>(out);
}

// round 10
// speedup vs baseline: 1.2718x; 1.0210x over previous
#include <cuda_runtime.h>
#include <cuda_bf16.h>

#define S_LEN 512
#define HID   500
#define G3    1500
#define VOC   50000
#define NVT   391          // ceil(50000/128)
#define RBLK  25           // recurrence blocks
#define RWPB  20           // warps per recurrence block (25*20 = 500 = HID)

// ---------------- static device scratch ----------------
__device__ float gGiEnc[S_LEN * G3];
__device__ float gGiDec[S_LEN * G3];
// mailbox lines: [parity][block] = 128B line: 20 h floats + flag word at [31]
__device__ __align__(128) float gHx[2][RBLK][32];
__device__ __align__(16) float gHfinal[512];
__device__ float gDecHs[S_LEN * HID];
__device__ float gPmax[S_LEN * NVT];
__device__ float gPsum[S_LEN * NVT];
__device__ int   gPidx[S_LEN * NVT];
__device__ float gTlogit[S_LEN];
__device__ float gNll[S_LEN];

// ---------------- helpers ----------------
__device__ __forceinline__ unsigned long long f22ull(float x, float y) {
    unsigned long long u;
    asm("mov.b64 %0, {%1, %2};" : "=l"(u) : "f"(x), "f"(y));
    return u;
}
__device__ __forceinline__ void ull2f2(unsigned long long u, float& x, float& y) {
    asm("mov.b64 {%0, %1}, %2;" : "=f"(x), "=f"(y) : "l"(u));
}
__device__ __forceinline__ void ffma2(unsigned long long& d, unsigned long long a, unsigned long long b) {
    asm("fma.rn.f32x2 %0, %1, %2, %0;" : "+l"(d) : "l"(a), "l"(b));
}
__device__ __forceinline__ unsigned ld_acq(const unsigned* p) {
    unsigned v;
    asm volatile("ld.acquire.gpu.global.u32 %0, [%1];" : "=r"(v) : "l"(p) : "memory");
    return v;
}
__device__ __forceinline__ void st_rel(unsigned* p, unsigned v) {
    asm volatile("st.release.gpu.global.u32 [%0], %1;" :: "l"(p), "r"(v) : "memory");
}

// =====================================================================
// K0: reset mailbox flags/data (replay safety). 2 x 800 covers 1600 floats.
// =====================================================================
__global__ void reset_kernel() {
    int i = blockIdx.x * blockDim.x + threadIdx.x;
    if (i < 2 * RBLK * 32) ((float*)gHx)[i] = 0.f;
}

// =====================================================================
// K1: gi = gather(emb, tok)[relu if dec] @ Wih^T + bih   for enc & dec
// grid (12, 4, 2). Conflict-free B fragments: thread tx owns cols tx+16m.
// =====================================================================
__global__ __launch_bounds__(256, 1) void gi_gemm_kernel(
    const int* __restrict__ encTok, const int* __restrict__ tgtTok,
    const float* __restrict__ encEmb, const float* __restrict__ decEmb,
    const float* __restrict__ encWih, const float* __restrict__ decWih,
    const float* __restrict__ encBih, const float* __restrict__ decBih)
{
    const int mode = blockIdx.z;
    const float* emb  = mode ? decEmb : encEmb;
    const float* W    = mode ? decWih : encWih;
    const float* bias = mode ? decBih : encBih;
    float* out = mode ? gGiDec : gGiEnc;

    const int t0 = blockIdx.y * 128;
    const int g0 = blockIdx.x * 128;

    __shared__ __align__(16) unsigned long long As[10][128];
    __shared__ __align__(16) unsigned long long Bs[10][128];
    __shared__ int   sTok[128];
    __shared__ float sBias[128];

    const int tid = threadIdx.x;
    if (tid < 128) {
        int t = t0 + tid;
        int tok;
        if (mode) tok = (t == 0) ? 0 : tgtTok[t - 1];   // teacher forcing, PAD first
        else      tok = encTok[t];
        sTok[tid] = tok;
        int g = g0 + tid;
        sBias[tid] = (g < G3) ? bias[g] : 0.f;
    }
    __syncthreads();

    unsigned long long acc[8][8];
#pragma unroll
    for (int i = 0; i < 8; i++)
#pragma unroll
        for (int j = 0; j < 8; j++) acc[i][j] = 0ull;

    const int ty = tid >> 4, tx = tid & 15;

    for (int kc = 0; kc < 25; kc++) {
        const int kb = kc * 20;
#pragma unroll
        for (int r = 0; r < 5; r++) {
            int id  = tid + r * 256;
            int k2  = id >> 7;
            int col = id & 127;
            const float* ap = emb + (size_t)sTok[col] * HID + kb + k2 * 2;
            float2 av = *(const float2*)ap;
            if (mode) { av.x = fmaxf(av.x, 0.f); av.y = fmaxf(av.y, 0.f); }
            As[k2][col] = f22ull(av.x, av.y);
            int g = g0 + col;
            float2 bv = make_float2(0.f, 0.f);
            if (g < G3) bv = *(const float2*)(W + (size_t)g * HID + kb + k2 * 2);
            Bs[k2][col] = f22ull(bv.x, bv.y);
        }
        __syncthreads();
#pragma unroll
        for (int k2 = 0; k2 < 10; k2++) {
            unsigned long long a[8], b[8];
            const ulonglong2* ap = (const ulonglong2*)&As[k2][ty << 3];
            ulonglong2 q;
            q = ap[0]; a[0] = q.x; a[1] = q.y;
            q = ap[1]; a[2] = q.x; a[3] = q.y;
            q = ap[2]; a[4] = q.x; a[5] = q.y;
            q = ap[3]; a[6] = q.x; a[7] = q.y;
#pragma unroll
            for (int m = 0; m < 8; m++) b[m] = Bs[k2][tx + (m << 4)];
#pragma unroll
            for (int i = 0; i < 8; i++)
#pragma unroll
                for (int j = 0; j < 8; j++) ffma2(acc[i][j], a[i], b[j]);
        }
        __syncthreads();
    }

#pragma unroll
    for (int i = 0; i < 8; i++) {
        int t = t0 + (ty << 3) + i;
#pragma unroll
        for (int m = 0; m < 8; m++) {
            int g = g0 + tx + (m << 4);
            if (g < G3) {
                float x, y; ull2f2(acc[i][m], x, y);
                out[(size_t)t * G3 + g] = x + y + sBias[tx + (m << 4)];
            }
        }
    }
}

// =====================================================================
// K2: GRU recurrence, persistent. 25 blocks x 640 threads (500 warps).
// Per-step exchange via per-block 128B mailbox lines (data+flag in one
// line => one L2 round trip), release/acquire, no atomics, no barrier.
// =====================================================================
__global__ __launch_bounds__(640, 1) void gru_rec_kernel(
    const float* __restrict__ Whh, const float* __restrict__ bhh,
    const float* __restrict__ h0_in, float* __restrict__ dOut,
    int mode, unsigned flagBase)
{
    const float* gi = mode ? gGiDec : gGiEnc;
    const int tid  = threadIdx.x;
    const int warp = tid >> 5;
    const int lane = tid & 31;
    const int j = blockIdx.x * RWPB + warp;   // 0..499

    __shared__ __align__(16) float sH[512];
    __shared__ __align__(16) float sStage[RWPB];

    // weights: lane holds k = i*128 + lane*4 + c  (float4 layout, zero-padded)
    float wr[16], wz[16], wn[16];
#pragma unroll
    for (int i = 0; i < 4; i++) {
        int kb = (i << 7) + (lane << 2);
        if (kb + 3 < HID) {
            float4 a = *(const float4*)(Whh + (size_t)j * HID + kb);
            float4 b = *(const float4*)(Whh + (size_t)(j + HID) * HID + kb);
            float4 c = *(const float4*)(Whh + (size_t)(j + 2 * HID) * HID + kb);
            wr[i*4+0]=a.x; wr[i*4+1]=a.y; wr[i*4+2]=a.z; wr[i*4+3]=a.w;
            wz[i*4+0]=b.x; wz[i*4+1]=b.y; wz[i*4+2]=b.z; wz[i*4+3]=b.w;
            wn[i*4+0]=c.x; wn[i*4+1]=c.y; wn[i*4+2]=c.z; wn[i*4+3]=c.w;
        } else {
#pragma unroll
            for (int c = 0; c < 4; c++) { wr[i*4+c]=0.f; wz[i*4+c]=0.f; wn[i*4+c]=0.f; }
        }
    }
    const float br = bhh[j], bz = bhh[j + HID], bn = bhh[j + 2 * HID];

    // init sH from h0 (enc) / gHfinal (dec); pad 500..511 with zeros
    if (tid < 128) {
        float4 v = make_float4(0.f, 0.f, 0.f, 0.f);
        if (tid < 125) {
            if (mode) v = *(const float4*)(gHfinal + tid * 4);
            else      v = *(const float4*)(h0_in + tid * 4);   // exactly 500 floats
        }
        *(float4*)(sH + tid * 4) = v;
    }

    // prefetch gi for step 0
    float gir = 0.f, giz = 0.f, gin = 0.f;
    if (lane == 0) {
        const float* g0 = gi + j;
        gir = g0[0]; giz = g0[HID]; gin = g0[2 * HID];
    }
    __syncthreads();

    for (int s = 0; s < S_LEN; s++) {
        // ---- compute: h from shared, dot with register weights ----
        float h[16];
#pragma unroll
        for (int i = 0; i < 4; i++) {
            float4 v = *(const float4*)(sH + (i << 7) + (lane << 2));
            h[i*4+0]=v.x; h[i*4+1]=v.y; h[i*4+2]=v.z; h[i*4+3]=v.w;
        }
        float ar = 0.f, az = 0.f, an = 0.f;
#pragma unroll
        for (int i = 0; i < 16; i++) {
            ar = fmaf(wr[i], h[i], ar);
            az = fmaf(wz[i], h[i], az);
            an = fmaf(wn[i], h[i], an);
        }
#pragma unroll
        for (int off = 16; off; off >>= 1) {
            ar += __shfl_xor_sync(0xffffffffu, ar, off);
            az += __shfl_xor_sync(0xffffffffu, az, off);
            an += __shfl_xor_sync(0xffffffffu, an, off);
        }
        if (lane == 0) {
            float hold = sH[j];
            float r = 1.f / (1.f + expf(-(gir + ar + br)));
            float z = 1.f / (1.f + expf(-(giz + az + bz)));
            float n = tanhf(gin + r * (an + bn));
            sStage[warp] = (1.f - z) * n + z * hold;
            if (s + 1 < S_LEN) {           // prefetch next gi — hides under exchange
                const float* gs = gi + (size_t)(s + 1) * G3 + j;
                gir = gs[0]; giz = gs[HID]; gin = gs[2 * HID];
            }
        }
        __syncthreads();                   // A: sStage complete, sH reads done

        const unsigned want = flagBase + 1u + (unsigned)s;
        if (warp == 0) {
            // ---- produce: one 128B mailbox line (data + release flag) ----
            if (lane == 0) {
                float* line = gHx[s & 1][blockIdx.x];
                float4 d0 = *(float4*)(sStage + 0);
                float4 d1 = *(float4*)(sStage + 4);
                float4 d2 = *(float4*)(sStage + 8);
                float4 d3 = *(float4*)(sStage + 12);
                float4 d4 = *(float4*)(sStage + 16);
                __stcg((float4*)line + 0, d0);
                __stcg((float4*)line + 1, d1);
                __stcg((float4*)line + 2, d2);
                __stcg((float4*)line + 3, d3);
                __stcg((float4*)line + 4, d4);
                if (mode) {
                    float4* hp = (float4*)(gDecHs + (size_t)s * HID + blockIdx.x * RWPB);
                    __stcg(hp + 0, d0); __stcg(hp + 1, d1); __stcg(hp + 2, d2);
                    __stcg(hp + 3, d3); __stcg(hp + 4, d4);
                }
                st_rel((unsigned*)(line + 31), want);   // orders prior stores
            }
            // ---- consume: lane b polls block b's flag, pulls same line ----
            if (lane < RBLK) {
                const float* line = gHx[s & 1][lane];
                const unsigned* fp = (const unsigned*)(line + 31);
                while (ld_acq(fp) < want) { }
                float4 v0 = __ldcg((const float4*)line + 0);
                float4 v1 = __ldcg((const float4*)line + 1);
                float4 v2 = __ldcg((const float4*)line + 2);
                float4 v3 = __ldcg((const float4*)line + 3);
                float4 v4 = __ldcg((const float4*)line + 4);
                float* dst = sH + lane * RWPB;
                *(float4*)(dst + 0)  = v0;
                *(float4*)(dst + 4)  = v1;
                *(float4*)(dst + 8)  = v2;
                *(float4*)(dst + 12) = v3;
                *(float4*)(dst + 16) = v4;
            }
        }
        __syncthreads();                   // B: sH holds step-s result
    }

    if (!mode && blockIdx.x == 0) {
        if (tid < 512) gHfinal[tid] = sH[tid];
        if (tid < HID) dOut[1 + tid] = sH[tid];   // enc_h output slice
    }
}

// =====================================================================
// K3: logits = dec_hs @ outW^T + outB, double-buffered smem, fused
// per-tile softmax partials. grid (NVT, 4). Logits never hit HBM.
// =====================================================================
__global__ __launch_bounds__(256, 1) void logits_kernel(
    const float* __restrict__ outW, const float* __restrict__ outB,
    const int* __restrict__ target)
{
    const int t0 = blockIdx.y * 128;
    const int v0 = blockIdx.x * 128;

    __shared__ __align__(16) unsigned long long As[2][10][128];  // 20 KB
    __shared__ __align__(16) unsigned long long Bs[2][10][128];  // 20 KB
    __shared__ float sOb[128];
    __shared__ float sRowMax[128];
    __shared__ int   sRowIdx[128];

    const int tid = threadIdx.x;
    if (tid < 128) {
        int v = v0 + tid;
        sOb[tid] = (v < VOC) ? outB[v] : 0.f;
    }

    unsigned long long acc[8][8];
#pragma unroll
    for (int i = 0; i < 8; i++)
#pragma unroll
        for (int j = 0; j < 8; j++) acc[i][j] = 0ull;

    const int ty = tid >> 4, tx = tid & 15;

    // prologue: chunk 0 straight to smem buffer 0
    {
#pragma unroll
        for (int r = 0; r < 5; r++) {
            int id  = tid + r * 256;
            int k2  = id >> 7;
            int col = id & 127;
            float2 av = *(const float2*)(gDecHs + (size_t)(t0 + col) * HID + k2 * 2);
            As[0][k2][col] = f22ull(av.x, av.y);
            int v = v0 + col;
            float2 bv = make_float2(0.f, 0.f);
            if (v < VOC) bv = *(const float2*)(outW + (size_t)v * HID + k2 * 2);
            Bs[0][k2][col] = f22ull(bv.x, bv.y);
        }
    }
    __syncthreads();

    for (int kc = 0; kc < 25; kc++) {
        const int cur = kc & 1, nxt = cur ^ 1;

        unsigned long long pa[5], pb[5];
        if (kc < 24) {
            const int kb = (kc + 1) * 20;
#pragma unroll
            for (int r = 0; r < 5; r++) {
                int id  = tid + r * 256;
                int k2  = id >> 7;
                int col = id & 127;
                float2 av = *(const float2*)(gDecHs + (size_t)(t0 + col) * HID + kb + k2 * 2);
                pa[r] = f22ull(av.x, av.y);
                int v = v0 + col;
                float2 bv = make_float2(0.f, 0.f);
                if (v < VOC) bv = *(const float2*)(outW + (size_t)v * HID + kb + k2 * 2);
                pb[r] = f22ull(bv.x, bv.y);
            }
        }

#pragma unroll
        for (int k2 = 0; k2 < 10; k2++) {
            unsigned long long a[8], b[8];
            const ulonglong2* ap = (const ulonglong2*)&As[cur][k2][ty << 3];
            ulonglong2 q;
            q = ap[0]; a[0] = q.x; a[1] = q.y;
            q = ap[1]; a[2] = q.x; a[3] = q.y;
            q = ap[2]; a[4] = q.x; a[5] = q.y;
            q = ap[3]; a[6] = q.x; a[7] = q.y;
#pragma unroll
            for (int m = 0; m < 8; m++) b[m] = Bs[cur][k2][tx + (m << 4)];
#pragma unroll
            for (int i = 0; i < 8; i++)
#pragma unroll
                for (int j = 0; j < 8; j++) ffma2(acc[i][j], a[i], b[j]);
        }

        if (kc < 24) {
#pragma unroll
            for (int r = 0; r < 5; r++) {
                int id  = tid + r * 256;
                int k2  = id >> 7;
                int col = id & 127;
                As[nxt][k2][col] = pa[r];
                Bs[nxt][k2][col] = pb[r];
            }
        }
        __syncthreads();
    }

    // ---- fused epilogue: per-(row, vtile) max / argmax / sum-exp ----
    float* sM = (float*)As;
    int*   sI = (int*)Bs;

#pragma unroll
    for (int i = 0; i < 8; i++) {
        int row = (ty << 3) + i;
        int t = t0 + row;
        int tgt = target[t];
        float lmax = -1e30f; int lidx = 0;
#pragma unroll
        for (int m = 0; m < 8; m++) {
            int v = v0 + tx + (m << 4);
            if (v < VOC) {
                float x, y; ull2f2(acc[i][m], x, y);
                float logit = x + y + sOb[tx + (m << 4)];
                if (logit > lmax) { lmax = logit; lidx = v; }
                if (v == tgt) gTlogit[t] = logit;
            }
        }
        sM[row * 16 + tx] = lmax;
        sI[row * 16 + tx] = lidx;
    }
    __syncthreads();

    if (tid < 128) {
        float m = -1e30f; int idx = 0x7fffffff;
        for (int e = 0; e < 16; e++) {
            float me = sM[tid * 16 + e]; int ie = sI[tid * 16 + e];
            if (me > m || (me == m && ie < idx)) { m = me; idx = ie; }
        }
        sRowMax[tid] = m; sRowIdx[tid] = idx;
    }
    __syncthreads();

    float* sS = (float*)As;
#pragma unroll
    for (int i = 0; i < 8; i++) {
        int row = (ty << 3) + i;
        float rmax = sRowMax[row];
        float lsum = 0.f;
#pragma unroll
        for (int m = 0; m < 8; m++) {
            int v = v0 + tx + (m << 4);
            if (v < VOC) {
                float x, y; ull2f2(acc[i][m], x, y);
                lsum += expf(x + y + sOb[tx + (m << 4)] - rmax);
            }
        }
        sS[row * 16 + tx] = lsum;
    }
    __syncthreads();

    if (tid < 128) {
        float s = 0.f;
        for (int e = 0; e < 16; e++) s += sS[tid * 16 + e];
        int t = t0 + tid;
        size_t o = (size_t)t * NVT + blockIdx.x;
        gPmax[o] = sRowMax[tid];
        gPidx[o] = sRowIdx[tid];
        gPsum[o] = s;
    }
}

// =====================================================================
// K4: per-row cross-tile reduction -> argmax + NLL.   grid(512) x 128
// =====================================================================
__global__ __launch_bounds__(128) void finalize_kernel(float* __restrict__ dOut)
{
    const int t = blockIdx.x;
    const int tid = threadIdx.x;
    __shared__ float rm[128];
    __shared__ int   ri[128];
    __shared__ float rs[128];

    float m = -1e30f; int idx = 0x7fffffff;
    for (int vt = tid; vt < NVT; vt += 128) {
        float mv = gPmax[(size_t)t * NVT + vt];
        int   iv = gPidx[(size_t)t * NVT + vt];
        if (mv > m || (mv == m && iv < idx)) { m = mv; idx = iv; }
    }
    rm[tid] = m; ri[tid] = idx;
    __syncthreads();
    for (int off = 64; off; off >>= 1) {
        if (tid < off) {
            float m2 = rm[tid + off]; int i2 = ri[tid + off];
            if (m2 > rm[tid] || (m2 == rm[tid] && i2 < ri[tid])) { rm[tid] = m2; ri[tid] = i2; }
        }
        __syncthreads();
    }
    float gmax = rm[0]; int gidx = ri[0];

    float s = 0.f;
    for (int vt = tid; vt < NVT; vt += 128) {
        size_t o = (size_t)t * NVT + vt;
        s += gPsum[o] * expf(gPmax[o] - gmax);
    }
    rs[tid] = s;
    __syncthreads();
    for (int off = 64; off; off >>= 1) {
        if (tid < off) rs[tid] += rs[tid + off];
        __syncthreads();
    }
    if (tid == 0) {
        float lse = gmax + logf(rs[0]);
        gNll[t] = lse - gTlogit[t];
        dOut[1 + HID + t] = (float)gidx;     // decoder_outputs
    }
}

// =====================================================================
// K5: loss = sum(gNll).   1 block x 512
// =====================================================================
__global__ __launch_bounds__(512) void loss_kernel(float* __restrict__ dOut)
{
    __shared__ float rs[512];
    int tid = threadIdx.x;
    rs[tid] = gNll[tid];
    __syncthreads();
    for (int off = 256; off; off >>= 1) {
        if (tid < off) rs[tid] += rs[tid + off];
        __syncthreads();
    }
    if (tid == 0) dOut[0] = rs[0];
}

// =====================================================================
extern "C" void kernel_launch(void* const* d_in, const int* in_sizes, int n_in,
                              void* d_out, int out_size)
{
    const int*   encTok = (const int*)d_in[0];
    const int*   tgtTok = (const int*)d_in[1];
    const float* encH0  = (const float*)d_in[2];
    const float* encEmb = (const float*)d_in[3];
    const float* encWih = (const float*)d_in[4];
    const float* encWhh = (const float*)d_in[5];
    const float* encBih = (const float*)d_in[6];
    const float* encBhh = (const float*)d_in[7];
    const float* decEmb = (const float*)d_in[8];
    const float* decWih = (const float*)d_in[9];
    const float* decWhh = (const float*)d_in[10];
    const float* decBih = (const float*)d_in[11];
    const float* decBhh = (const float*)d_in[12];
    const float* outW   = (const float*)d_in[13];
    const float* outB   = (const float*)d_in[14];
    float* out = (float*)d_out;

    reset_kernel<<<2, 800>>>();
    gi_gemm_kernel<<<dim3(12, 4, 2), 256>>>(encTok, tgtTok, encEmb, decEmb,
                                            encWih, decWih, encBih, decBih);
    gru_rec_kernel<<<RBLK, 640>>>(encWhh, encBhh, encH0, out, 0, 0u);
    gru_rec_kernel<<<RBLK, 640>>>(decWhh, decBhh, encH0, out, 1, 512u);
    logits_kernel<<<dim3(NVT, 4), 256>>>(outW, outB, tgtTok);
    finalize_kernel<<<512, 128>>>(out);
    loss_kernel<<<1, 512>>>(out);
}